// round 16
// baseline (speedup 1.0000x reference)
#include <cuda_runtime.h>
#include <cuda_bf16.h>
#include <cuda_fp16.h>
#include <stdint.h>
#include <math.h>

#define BB   4
#define NN   8192
#define CC   256
#define DD   256
#define LSEG 2048
#define NSEG 28

// ---------------- cp.async helpers -----------------------------------------
__device__ __forceinline__ uint32_t smem_to_u32(const void* p) {
    uint32_t a;
    asm("{ .reg .u64 t; cvta.to.shared.u64 t, %1; cvt.u32.u64 %0, t; }"
        : "=r"(a) : "l"(p));
    return a;
}
__device__ __forceinline__ void cp16(uint32_t dst, const void* src) {
    asm volatile("cp.async.cg.shared.global [%0], [%1], 16;" :: "r"(dst), "l"(src) : "memory");
}
#define CP_COMMIT() asm volatile("cp.async.commit_group;" ::: "memory")
#define CP_WAIT1()  asm volatile("cp.async.wait_group 1;" ::: "memory")
#define CP_WAIT0()  asm volatile("cp.async.wait_group 0;" ::: "memory")

// ---------------- ldmatrix / mma.sync ---------------------------------------
__device__ __forceinline__ void ldsm4(uint32_t (&d)[4], uint32_t addr) {
    asm volatile("ldmatrix.sync.aligned.m8n8.x4.shared.b16 {%0,%1,%2,%3}, [%4];"
        : "=r"(d[0]), "=r"(d[1]), "=r"(d[2]), "=r"(d[3]) : "r"(addr));
}
__device__ __forceinline__ void ldsm4t(uint32_t (&d)[4], uint32_t addr) {
    asm volatile("ldmatrix.sync.aligned.m8n8.x4.trans.shared.b16 {%0,%1,%2,%3}, [%4];"
        : "=r"(d[0]), "=r"(d[1]), "=r"(d[2]), "=r"(d[3]) : "r"(addr));
}
__device__ __forceinline__ void mma_fp16(float (&c)[4], const uint32_t (&a)[4],
                                         uint32_t b0, uint32_t b1) {
    asm volatile("mma.sync.aligned.m16n8k16.row.col.f32.f16.f16.f32 "
        "{%0,%1,%2,%3}, {%4,%5,%6,%7}, {%8,%9}, {%0,%1,%2,%3};"
        : "+f"(c[0]), "+f"(c[1]), "+f"(c[2]), "+f"(c[3])
        : "r"(a[0]), "r"(a[1]), "r"(a[2]), "r"(a[3]), "r"(b0), "r"(b1));
}

// A-fragment address (ldmatrix x4): 16 rows starting r0, k-step ks (16 elems)
__device__ __forceinline__ uint32_t aAddr(uint32_t base, int rowbytes, int r0,
                                          int ks, int lane) {
    int row = r0 + (lane & 7) + ((lane & 8) ? 8 : 0);
    int c16 = ks * 2 + (lane >> 4);
    return base + row * rowbytes + ((uint32_t)(c16 ^ (row & 7)) << 4);
}
// B-fragment address (ldmatrix x4): 8 rows at n0, TWO k-steps (pair kp)
__device__ __forceinline__ uint32_t b4Addr(uint32_t base, int rowbytes, int n0,
                                           int kp, int lane) {
    int row = n0 + (lane & 7);
    int c16 = kp * 4 + (lane >> 3);
    return base + row * rowbytes + ((uint32_t)(c16 ^ (row & 7)) << 4);
}
// trans B-fragment address (ldmatrix x4 .trans): 16 key-rows at k0, two n8
// tiles at 16B-chunks c16base, c16base+1 of a key-major matrix.
__device__ __forceinline__ uint32_t bTAddr(uint32_t base, int rowbytes, int k0,
                                           int c16base, int lane) {
    int row = k0 + (lane & 7) + ((lane & 8) ? 8 : 0);
    int c16 = c16base + (lane >> 4);
    return base + row * rowbytes + ((uint32_t)(c16 ^ (row & 7)) << 4);
}
__device__ __forceinline__ uint32_t swz512(uint32_t base, int row, int c16) {
    return base + row * 512 + ((uint32_t)(c16 ^ (row & 7)) << 4);
}
__device__ __forceinline__ uint32_t swz128(uint32_t base, int row, int c16) {
    return base + row * 128 + ((uint32_t)(c16 ^ (row & 7)) << 4);
}

// ---------------- scratch ---------------------------------------------------
__device__ __half        g_Xf [BB * NN * CC];       // X single fp16
__device__ __half        g_Wf [3 * CC * DD];        // [z][n][k] transposed, fp16
__device__ __half        g_Qf [BB * NN * DD];       // Q single fp16 (x 1/16)
__device__ __half        g_Kf [BB * NN * DD];       // K single fp16
__device__ __half        g_Vf [BB * NN * DD];       // V single fp16 (token-major)
__device__ float g_O[NSEG * LSEG * DD];
__device__ float g_den[NSEG * LSEG];

__device__ __forceinline__ void slot_decode(int s, int& batch, int& posbase, int& r) {
    int w, base;
    if (s < 16)      { w = 2048; r = 1; base = 0;  }
    else if (s < 24) { w = 4096; r = 2; base = 16; }
    else             { w = 8192; r = 4; base = 24; }
    int local = s - base;
    batch = local & 3;
    posbase = (local >> 2) * w;
}

// ================= Phase 0a: convert X to single fp16 =======================
__global__ __launch_bounds__(256) void split_x_kernel(const float* __restrict__ X)
{
    long e = (long)blockIdx.x * 1024 + threadIdx.x * 4;
    float4 v = *(const float4*)(X + e);
    *(__half2*)(g_Xf + e)     = __floats2half2_rn(v.x, v.y);
    *(__half2*)(g_Xf + e + 2) = __floats2half2_rn(v.z, v.w);
}

// ================= Phase 0b: transpose W -> single fp16 =====================
__global__ __launch_bounds__(256) void split_w_kernel(
    const float* __restrict__ Wq, const float* __restrict__ Wk,
    const float* __restrict__ Wv)
{
    __shared__ float T[32][33];
    const int z = blockIdx.z;
    const float* W = (z == 0) ? Wq : (z == 1) ? Wk : Wv;
    const int k0 = blockIdx.x * 32, n0 = blockIdx.y * 32;
    const int t = threadIdx.x;
    {
        int kk = t >> 3, n4 = (t & 7) << 2;
        float4 v = *(const float4*)(W + (long)(k0 + kk) * DD + n0 + n4);
        T[kk][n4] = v.x; T[kk][n4 + 1] = v.y; T[kk][n4 + 2] = v.z; T[kk][n4 + 3] = v.w;
    }
    __syncthreads();
    {
        int nn = t >> 3, k4 = (t & 7) << 2;
        float sc = (z == 0) ? 0.0625f : 1.0f;
        __half2 h0 = __floats2half2_rn(T[k4][nn] * sc, T[k4 + 1][nn] * sc);
        __half2 h1 = __floats2half2_rn(T[k4 + 2][nn] * sc, T[k4 + 3][nn] * sc);
        long off = (long)z * (CC * DD) + (long)(n0 + nn) * CC + k0 + k4;
        *(__half2*)(g_Wf + off) = h0; *(__half2*)(g_Wf + off + 2) = h1;
    }
}

// ================= Phase 1: QKV projection via mma.sync =====================
// X single fp16 x W single fp16: 1 term.
#define GX   0
#define GW   32768
#define QKV_SMEM 65536

__global__ __launch_bounds__(256, 2) void qkv_mma_kernel()
{
    extern __shared__ char smem[];
    const uint32_t sb = smem_to_u32(smem);
    const int t = threadIdx.x, lane = t & 31, wid = t >> 5;
    const int m0 = blockIdx.x * 128, n0 = blockIdx.y * 128, z = blockIdx.z;
    const __half* Wt = g_Wf + (long)z * (CC * DD);

    auto loadslab = [&](int s, int buf) {
        int k0 = s * 64;
        uint32_t bo = (uint32_t)buf * 16384;
#pragma unroll
        for (int i = 0; i < 4; i++) {
            int e = t + i * 256;
            int row = e >> 3, c16 = e & 7;
            cp16(swz128(sb + GX + bo, row, c16),
                 (const void*)(g_Xf + (long)(m0 + row) * CC + k0 + c16 * 8));
            cp16(swz128(sb + GW + bo, row, c16),
                 (const void*)(Wt + (long)(n0 + row) * CC + k0 + c16 * 8));
        }
    };

    float acc[16][4];
#pragma unroll
    for (int nt = 0; nt < 16; nt++)
#pragma unroll
        for (int c = 0; c < 4; c++) acc[nt][c] = 0.f;

    loadslab(0, 0); CP_COMMIT();
    for (int s = 0; s < 4; s++) {
        if (s < 3) { loadslab(s + 1, (s + 1) & 1); CP_COMMIT(); CP_WAIT1(); }
        else CP_WAIT0();
        __syncthreads();
        uint32_t bo = (uint32_t)(s & 1) * 16384;
#pragma unroll
        for (int kp = 0; kp < 2; kp++) {
            uint32_t af0[4], af1[4];
            ldsm4(af0, aAddr(sb + GX + bo, 128, wid * 16, 2 * kp,     lane));
            ldsm4(af1, aAddr(sb + GX + bo, 128, wid * 16, 2 * kp + 1, lane));
#pragma unroll
            for (int nt = 0; nt < 16; nt++) {
                uint32_t bh[4];
                ldsm4(bh, b4Addr(sb + GW + bo, 128, nt * 8, kp, lane));
                mma_fp16(acc[nt], af0, bh[0], bh[1]);
                mma_fp16(acc[nt], af1, bh[2], bh[3]);
            }
        }
        __syncthreads();
    }

    const int g = lane >> 2, cpair = 2 * (lane & 3);
    __half* dst = (z == 0) ? g_Qf : (z == 1) ? g_Kf : g_Vf;
#pragma unroll
    for (int nt = 0; nt < 16; nt++) {
        long r0 = (long)(m0 + wid * 16 + g) * DD + n0 + nt * 8 + cpair;
        long r1 = r0 + 8 * DD;
        *(__half2*)(dst + r0) = __floats2half2_rn(acc[nt][0], acc[nt][1]);
        *(__half2*)(dst + r1) = __floats2half2_rn(acc[nt][2], acc[nt][3]);
    }
}

// ================= Phase 2: mma.sync fp16 causal attention ==================
// 128-query tile, 512 threads (16 warps), 1 CTA/SM. Same 3-barrier chunk
// structure; per-chunk overheads amortized over 2x the MMA work.
#define OQ  0
#define OK  65536
#define OV  98304
#define OP  131072
#define OLS 147456
#define SM_TOTAL (OLS + 1024)

__global__ __launch_bounds__(512, 1) void attn_kernel()
{
    extern __shared__ char smem[];
    const uint32_t sb = smem_to_u32(smem);
    float* lsum2 = (float*)(smem + OLS);          // [2][128]

    const int t = threadIdx.x, lane = t & 31, wid = t >> 5;
    const int qt = 15 - (int)blockIdx.x;          // heavy tiles first
    const int s  = blockIdx.y;
    int batch, posbase, r;
    slot_decode(s, batch, posbase, r);
    const long qkvoff = (long)batch * (NN * DD);

    auto issueK = [&](int kt) {
#pragma unroll
        for (int i = 0; i < 4; i++) {
            int e = t + i * 512;
            int key = e >> 5, c16 = e & 31;
            cp16(swz512(sb + OK, key, c16),
                 (const void*)(g_Kf + qkvoff +
                 ((long)(posbase + (kt * 64 + key) * r)) * DD + c16 * 8));
        }
    };
    auto issueV = [&](int kt) {
#pragma unroll
        for (int i = 0; i < 4; i++) {
            int e = t + i * 512;
            int key = e >> 5, c16 = e & 31;
            cp16(swz512(sb + OV, key, c16),
                 (const void*)(g_Vf + qkvoff +
                 ((long)(posbase + (kt * 64 + key) * r)) * DD + c16 * 8));
        }
    };

    // prologue: Q tile (128 rows) + K(0) in ONE commit group
    {
#pragma unroll
        for (int i = 0; i < 8; i++) {
            int e = t + i * 512;
            int row = e >> 5, c16 = e & 31;
            cp16(swz512(sb + OQ, row, c16),
                 (const void*)(g_Qf + qkvoff +
                 ((long)(posbase + (qt * 128 + row) * r)) * DD + c16 * 8));
        }
        issueK(0);
        CP_COMMIT();
    }

    const int g = lane >> 2, cpair = 2 * (lane & 3);
    const int wq = wid & 7, wk = wid >> 3;        // S: 8 q-groups x 2 k-groups
    const int prow0 = wq * 16 + g, prow1 = prow0 + 8;
    const int qrow0 = qt * 128 + prow0, qrow1 = qt * 128 + prow1;

    float accd[8][2][4];                          // PV: 128q x 16 d-cols / warp
#pragma unroll
    for (int mt = 0; mt < 8; mt++)
#pragma unroll
        for (int nt = 0; nt < 2; nt++)
#pragma unroll
            for (int c = 0; c < 4; c++) accd[mt][nt][c] = 0.f;
    float rs0 = 0.f, rs1 = 0.f;

    const int nchunks = 2 * qt + 2;
    for (int kt = 0; kt < nchunks; kt++) {
        CP_WAIT0();                               // K(kt) (+Q on kt=0) landed (mine)
        __syncthreads();                          // all K landed; prev PV done

        issueV(kt); CP_COMMIT();                  // overlaps S phase

        // ---- S = Q K^T: warp does 16q x 32k, single fp16 term -------------
        float sacc[4][4];
#pragma unroll
        for (int nt = 0; nt < 4; nt++)
#pragma unroll
            for (int c = 0; c < 4; c++) sacc[nt][c] = 0.f;
#pragma unroll 4
        for (int kp = 0; kp < 8; kp++) {
            uint32_t ah0[4], ah1[4];
            ldsm4(ah0, aAddr(sb + OQ, 512, wq * 16, 2 * kp,     lane));
            ldsm4(ah1, aAddr(sb + OQ, 512, wq * 16, 2 * kp + 1, lane));
#pragma unroll
            for (int nt = 0; nt < 4; nt++) {
                uint32_t bh[4];
                ldsm4(bh, b4Addr(sb + OK, 512, wk * 32 + nt * 8, kp, lane));
                mma_fp16(sacc[nt], ah0, bh[0], bh[1]);
                mma_fp16(sacc[nt], ah1, bh[2], bh[3]);
            }
        }

        // ---- softmax: mask, exp, row-sum, pack P (single fp16) -------------
#pragma unroll
        for (int nt = 0; nt < 4; nt++) {
            int kcol = wk * 32 + nt * 8 + cpair;
            int kg = kt * 64 + kcol;
            float p00 = (kg     <= qrow0) ? __expf(sacc[nt][0]) : 0.f;
            float p01 = (kg + 1 <= qrow0) ? __expf(sacc[nt][1]) : 0.f;
            float p10 = (kg     <= qrow1) ? __expf(sacc[nt][2]) : 0.f;
            float p11 = (kg + 1 <= qrow1) ? __expf(sacc[nt][3]) : 0.f;
            rs0 += p00 + p01;
            rs1 += p10 + p11;
            __half2 h0 = __floats2half2_rn(p00, p01);
            __half2 h1 = __floats2half2_rn(p10, p11);
            uint32_t ob0 = prow0 * 128 + ((uint32_t)((kcol >> 3) ^ (prow0 & 7)) << 4)
                         + (kcol & 7) * 2;
            uint32_t ob1 = prow1 * 128 + ((uint32_t)((kcol >> 3) ^ (prow1 & 7)) << 4)
                         + (kcol & 7) * 2;
            *(__half2*)(smem + OP + ob0) = h0;
            *(__half2*)(smem + OP + ob1) = h1;
        }
        __syncthreads();                          // P visible; K buf free

        // ---- prefetch next K (overlaps PV), then wait V --------------------
        if (kt + 1 < nchunks) { issueK(kt + 1); CP_COMMIT(); CP_WAIT1(); }
        else CP_WAIT0();
        __syncthreads();                          // V visible to all

        // ---- D += P V: warp owns 16 d-cols, all 128 q rows -----------------
        const int c16b = wid * 2;                 // d-cols [wid*16, wid*16+16)
#pragma unroll
        for (int kp = 0; kp < 4; kp++) {          // 16 keys per step
            uint32_t bt[4];
            ldsm4t(bt, bTAddr(sb + OV, 512, kp * 16, c16b, lane));
#pragma unroll
            for (int mt = 0; mt < 8; mt++) {
                uint32_t ah[4];
                ldsm4(ah, aAddr(sb + OP, 128, mt * 16, kp, lane));
                mma_fp16(accd[mt][0], ah, bt[0], bt[1]);
                mma_fp16(accd[mt][1], ah, bt[2], bt[3]);
            }
        }
    }

    // ---- epilogue ---------------------------------------------------------
    rs0 += __shfl_xor_sync(0xffffffffu, rs0, 1);
    rs0 += __shfl_xor_sync(0xffffffffu, rs0, 2);
    rs1 += __shfl_xor_sync(0xffffffffu, rs1, 1);
    rs1 += __shfl_xor_sync(0xffffffffu, rs1, 2);
    if ((lane & 3) == 0) {
        lsum2[wk * 128 + wq * 16 + g]     = rs0;
        lsum2[wk * 128 + wq * 16 + g + 8] = rs1;
    }
    __syncthreads();

#pragma unroll
    for (int mt = 0; mt < 8; mt++) {
        int lr0 = mt * 16 + g, lr1 = lr0 + 8;
        float inv0 = 1.0f / (lsum2[lr0] + lsum2[128 + lr0]);
        float inv1 = 1.0f / (lsum2[lr1] + lsum2[128 + lr1]);
        long ro0 = (long)(s * LSEG + qt * 128 + lr0) * DD;
        long ro1 = (long)(s * LSEG + qt * 128 + lr1) * DD;
#pragma unroll
        for (int nt = 0; nt < 2; nt++) {
            int col = wid * 16 + nt * 8 + cpair;
            *(float2*)(g_O + ro0 + col) =
                make_float2(accd[mt][nt][0] * inv0, accd[mt][nt][1] * inv0);
            *(float2*)(g_O + ro1 + col) =
                make_float2(accd[mt][nt][2] * inv1, accd[mt][nt][3] * inv1);
        }
    }
    if (t < 128)
        g_den[s * LSEG + qt * 128 + t] = lsum2[t] + lsum2[128 + t];
}

// ================= Phase 3: combine (gather) ================================
__global__ __launch_bounds__(256) void combine_kernel(float* __restrict__ out)
{
    const int token = blockIdx.x * 4 + (threadIdx.x >> 6);
    const int lane  = threadIdx.x & 63;
    const int b = token >> 13, p = token & 8191;

    const int slot0 = (p >> 11) * 4 + b, j0 = p & 2047;
    float d0 = g_den[slot0 * LSEG + j0];
    float sum = d0;
    int slot1 = -1, j1 = 0, slot2 = -1, j2 = 0;
    float d1 = 0.f, d2 = 0.f;
    if ((p & 1) == 0) {
        slot1 = 16 + (p >> 12) * 4 + b; j1 = (p & 4095) >> 1;
        d1 = g_den[slot1 * LSEG + j1]; sum += d1;
    }
    if ((p & 3) == 0) {
        slot2 = 24 + b; j2 = p >> 2;
        d2 = g_den[slot2 * LSEG + j2]; sum += d2;
    }
    const float inv = 1.0f / sum;
    const int c = lane << 2;

    float4 o0 = *(const float4*)(g_O + ((long)slot0 * LSEG + j0) * DD + c);
    float a0 = d0 * inv;
    float4 res;
    res.x = o0.x * a0; res.y = o0.y * a0; res.z = o0.z * a0; res.w = o0.w * a0;
    if (slot1 >= 0) {
        float4 o1 = *(const float4*)(g_O + ((long)slot1 * LSEG + j1) * DD + c);
        float a1 = d1 * inv;
        res.x = fmaf(o1.x, a1, res.x); res.y = fmaf(o1.y, a1, res.y);
        res.z = fmaf(o1.z, a1, res.z); res.w = fmaf(o1.w, a1, res.w);
    }
    if (slot2 >= 0) {
        float4 o2v = *(const float4*)(g_O + ((long)slot2 * LSEG + j2) * DD + c);
        float a2 = d2 * inv;
        res.x = fmaf(o2v.x, a2, res.x); res.y = fmaf(o2v.y, a2, res.y);
        res.z = fmaf(o2v.z, a2, res.z); res.w = fmaf(o2v.w, a2, res.w);
    }
    *(float4*)(out + ((long)b * NN + p) * DD + c) = res;
}

// ================= launch ====================================================
extern "C" void kernel_launch(void* const* d_in, const int* in_sizes, int n_in,
                              void* d_out, int out_size)
{
    (void)in_sizes; (void)n_in; (void)out_size;
    const float* x  = (const float*)d_in[0];
    const float* Wq = (const float*)d_in[1];
    const float* Wk = (const float*)d_in[2];
    const float* Wv = (const float*)d_in[3];

    cudaFuncSetAttribute(qkv_mma_kernel, cudaFuncAttributeMaxDynamicSharedMemorySize,
                         QKV_SMEM);
    cudaFuncSetAttribute(attn_kernel, cudaFuncAttributeMaxDynamicSharedMemorySize,
                         SM_TOTAL);

    split_x_kernel<<<8192, 256>>>(x);
    split_w_kernel<<<dim3(8, 8, 3), 256>>>(Wq, Wk, Wv);
    qkv_mma_kernel<<<dim3(256, 2, 3), 256, QKV_SMEM>>>();
    attn_kernel<<<dim3(16, 28), 512, SM_TOTAL>>>();
    combine_kernel<<<8192, 256>>>((float*)d_out);
}

// round 17
// speedup vs baseline: 1.3454x; 1.3454x over previous
#include <cuda_runtime.h>
#include <cuda_bf16.h>
#include <cuda_fp16.h>
#include <stdint.h>
#include <math.h>

#define BB   4
#define NN   8192
#define CC   256
#define DD   256
#define LSEG 2048
#define NSEG 28

// ---------------- cp.async helpers -----------------------------------------
__device__ __forceinline__ uint32_t smem_to_u32(const void* p) {
    uint32_t a;
    asm("{ .reg .u64 t; cvta.to.shared.u64 t, %1; cvt.u32.u64 %0, t; }"
        : "=r"(a) : "l"(p));
    return a;
}
__device__ __forceinline__ void cp16(uint32_t dst, const void* src) {
    asm volatile("cp.async.cg.shared.global [%0], [%1], 16;" :: "r"(dst), "l"(src) : "memory");
}
#define CP_COMMIT() asm volatile("cp.async.commit_group;" ::: "memory")
#define CP_WAIT1()  asm volatile("cp.async.wait_group 1;" ::: "memory")
#define CP_WAIT0()  asm volatile("cp.async.wait_group 0;" ::: "memory")

// ---------------- ldmatrix / mma.sync ---------------------------------------
__device__ __forceinline__ void ldsm4(uint32_t (&d)[4], uint32_t addr) {
    asm volatile("ldmatrix.sync.aligned.m8n8.x4.shared.b16 {%0,%1,%2,%3}, [%4];"
        : "=r"(d[0]), "=r"(d[1]), "=r"(d[2]), "=r"(d[3]) : "r"(addr));
}
__device__ __forceinline__ void ldsm4t(uint32_t (&d)[4], uint32_t addr) {
    asm volatile("ldmatrix.sync.aligned.m8n8.x4.trans.shared.b16 {%0,%1,%2,%3}, [%4];"
        : "=r"(d[0]), "=r"(d[1]), "=r"(d[2]), "=r"(d[3]) : "r"(addr));
}
__device__ __forceinline__ void mma_fp16(float (&c)[4], const uint32_t (&a)[4],
                                         uint32_t b0, uint32_t b1) {
    asm volatile("mma.sync.aligned.m16n8k16.row.col.f32.f16.f16.f32 "
        "{%0,%1,%2,%3}, {%4,%5,%6,%7}, {%8,%9}, {%0,%1,%2,%3};"
        : "+f"(c[0]), "+f"(c[1]), "+f"(c[2]), "+f"(c[3])
        : "r"(a[0]), "r"(a[1]), "r"(a[2]), "r"(a[3]), "r"(b0), "r"(b1));
}

// A-fragment address (ldmatrix x4): 16 rows starting r0, k-step ks (16 elems)
__device__ __forceinline__ uint32_t aAddr(uint32_t base, int rowbytes, int r0,
                                          int ks, int lane) {
    int row = r0 + (lane & 7) + ((lane & 8) ? 8 : 0);
    int c16 = ks * 2 + (lane >> 4);
    return base + row * rowbytes + ((uint32_t)(c16 ^ (row & 7)) << 4);
}
// B-fragment address (ldmatrix x4): 8 rows at n0, TWO k-steps (pair kp)
__device__ __forceinline__ uint32_t b4Addr(uint32_t base, int rowbytes, int n0,
                                           int kp, int lane) {
    int row = n0 + (lane & 7);
    int c16 = kp * 4 + (lane >> 3);
    return base + row * rowbytes + ((uint32_t)(c16 ^ (row & 7)) << 4);
}
// trans B-fragment address (ldmatrix x4 .trans): 16 key-rows at k0, two n8
// tiles at 16B-chunks c16base, c16base+1 of a key-major matrix.
__device__ __forceinline__ uint32_t bTAddr(uint32_t base, int rowbytes, int k0,
                                           int c16base, int lane) {
    int row = k0 + (lane & 7) + ((lane & 8) ? 8 : 0);
    int c16 = c16base + (lane >> 4);
    return base + row * rowbytes + ((uint32_t)(c16 ^ (row & 7)) << 4);
}
__device__ __forceinline__ uint32_t swz512(uint32_t base, int row, int c16) {
    return base + row * 512 + ((uint32_t)(c16 ^ (row & 7)) << 4);
}
__device__ __forceinline__ uint32_t swz128(uint32_t base, int row, int c16) {
    return base + row * 128 + ((uint32_t)(c16 ^ (row & 7)) << 4);
}

// ---------------- scratch ---------------------------------------------------
__device__ __half        g_Xf [BB * NN * CC];       // X single fp16
__device__ __half        g_Wf [3 * CC * DD];        // [z][n][k] transposed, fp16
__device__ __half        g_Qf [BB * NN * DD];       // Q single fp16 (x 1/16)
__device__ __half        g_Kf [BB * NN * DD];       // K single fp16
__device__ __half        g_Vf [BB * NN * DD];       // V single fp16 (token-major)
__device__ float g_O[NSEG * LSEG * DD];
__device__ float g_den[NSEG * LSEG];

__device__ __forceinline__ void slot_decode(int s, int& batch, int& posbase, int& r) {
    int w, base;
    if (s < 16)      { w = 2048; r = 1; base = 0;  }
    else if (s < 24) { w = 4096; r = 2; base = 16; }
    else             { w = 8192; r = 4; base = 24; }
    int local = s - base;
    batch = local & 3;
    posbase = (local >> 2) * w;
}

// ================= Phase 0a: convert X to single fp16 =======================
__global__ __launch_bounds__(256) void split_x_kernel(const float* __restrict__ X)
{
    long e = (long)blockIdx.x * 1024 + threadIdx.x * 4;
    float4 v = *(const float4*)(X + e);
    *(__half2*)(g_Xf + e)     = __floats2half2_rn(v.x, v.y);
    *(__half2*)(g_Xf + e + 2) = __floats2half2_rn(v.z, v.w);
}

// ================= Phase 0b: transpose W -> single fp16 =====================
__global__ __launch_bounds__(256) void split_w_kernel(
    const float* __restrict__ Wq, const float* __restrict__ Wk,
    const float* __restrict__ Wv)
{
    __shared__ float T[32][33];
    const int z = blockIdx.z;
    const float* W = (z == 0) ? Wq : (z == 1) ? Wk : Wv;
    const int k0 = blockIdx.x * 32, n0 = blockIdx.y * 32;
    const int t = threadIdx.x;
    {
        int kk = t >> 3, n4 = (t & 7) << 2;
        float4 v = *(const float4*)(W + (long)(k0 + kk) * DD + n0 + n4);
        T[kk][n4] = v.x; T[kk][n4 + 1] = v.y; T[kk][n4 + 2] = v.z; T[kk][n4 + 3] = v.w;
    }
    __syncthreads();
    {
        int nn = t >> 3, k4 = (t & 7) << 2;
        float sc = (z == 0) ? 0.0625f : 1.0f;
        __half2 h0 = __floats2half2_rn(T[k4][nn] * sc, T[k4 + 1][nn] * sc);
        __half2 h1 = __floats2half2_rn(T[k4 + 2][nn] * sc, T[k4 + 3][nn] * sc);
        long off = (long)z * (CC * DD) + (long)(n0 + nn) * CC + k0 + k4;
        *(__half2*)(g_Wf + off) = h0; *(__half2*)(g_Wf + off + 2) = h1;
    }
}

// ================= Phase 1: QKV projection via mma.sync =====================
// X single fp16 x W single fp16: 1 term.
#define GX   0
#define GW   32768
#define QKV_SMEM 65536

__global__ __launch_bounds__(256, 2) void qkv_mma_kernel()
{
    extern __shared__ char smem[];
    const uint32_t sb = smem_to_u32(smem);
    const int t = threadIdx.x, lane = t & 31, wid = t >> 5;
    const int m0 = blockIdx.x * 128, n0 = blockIdx.y * 128, z = blockIdx.z;
    const __half* Wt = g_Wf + (long)z * (CC * DD);

    auto loadslab = [&](int s, int buf) {
        int k0 = s * 64;
        uint32_t bo = (uint32_t)buf * 16384;
#pragma unroll
        for (int i = 0; i < 4; i++) {
            int e = t + i * 256;
            int row = e >> 3, c16 = e & 7;
            cp16(swz128(sb + GX + bo, row, c16),
                 (const void*)(g_Xf + (long)(m0 + row) * CC + k0 + c16 * 8));
            cp16(swz128(sb + GW + bo, row, c16),
                 (const void*)(Wt + (long)(n0 + row) * CC + k0 + c16 * 8));
        }
    };

    float acc[16][4];
#pragma unroll
    for (int nt = 0; nt < 16; nt++)
#pragma unroll
        for (int c = 0; c < 4; c++) acc[nt][c] = 0.f;

    loadslab(0, 0); CP_COMMIT();
    for (int s = 0; s < 4; s++) {
        if (s < 3) { loadslab(s + 1, (s + 1) & 1); CP_COMMIT(); CP_WAIT1(); }
        else CP_WAIT0();
        __syncthreads();
        uint32_t bo = (uint32_t)(s & 1) * 16384;
#pragma unroll
        for (int kp = 0; kp < 2; kp++) {
            uint32_t af0[4], af1[4];
            ldsm4(af0, aAddr(sb + GX + bo, 128, wid * 16, 2 * kp,     lane));
            ldsm4(af1, aAddr(sb + GX + bo, 128, wid * 16, 2 * kp + 1, lane));
#pragma unroll
            for (int nt = 0; nt < 16; nt++) {
                uint32_t bh[4];
                ldsm4(bh, b4Addr(sb + GW + bo, 128, nt * 8, kp, lane));
                mma_fp16(acc[nt], af0, bh[0], bh[1]);
                mma_fp16(acc[nt], af1, bh[2], bh[3]);
            }
        }
        __syncthreads();
    }

    const int g = lane >> 2, cpair = 2 * (lane & 3);
    __half* dst = (z == 0) ? g_Qf : (z == 1) ? g_Kf : g_Vf;
#pragma unroll
    for (int nt = 0; nt < 16; nt++) {
        long r0 = (long)(m0 + wid * 16 + g) * DD + n0 + nt * 8 + cpair;
        long r1 = r0 + 8 * DD;
        *(__half2*)(dst + r0) = __floats2half2_rn(acc[nt][0], acc[nt][1]);
        *(__half2*)(dst + r1) = __floats2half2_rn(acc[nt][2], acc[nt][3]);
    }
}

// ================= Phase 2: mma.sync fp16 causal attention ==================
// R15 structure (2 CTAs/SM, 64-q tiles, 3 barriers/chunk) with GLOBAL
// heavy-first CTA ordering: 1D grid, bid -> (tile rank, segment).
#define OQ  0
#define OK  32768
#define OV  65536
#define OP  98304
#define OLS 106496
#define SM_TOTAL (OLS + 512)

__global__ __launch_bounds__(256, 2) void attn_kernel()
{
    extern __shared__ char smem[];
    const uint32_t sb = smem_to_u32(smem);
    float* lsum2 = (float*)(smem + OLS);

    const int t = threadIdx.x, lane = t & 31, wid = t >> 5;
    const int bid = (int)blockIdx.x;
    const int qt = 31 - (bid / NSEG);             // all segments' rank-k together
    const int s  = bid % NSEG;
    int batch, posbase, r;
    slot_decode(s, batch, posbase, r);
    const long qkvoff = (long)batch * (NN * DD);

    auto issueK = [&](int kt) {
#pragma unroll
        for (int i = 0; i < 8; i++) {
            int e = t + i * 256;
            int key = e >> 5, c16 = e & 31;
            cp16(swz512(sb + OK, key, c16),
                 (const void*)(g_Kf + qkvoff +
                 ((long)(posbase + (kt * 64 + key) * r)) * DD + c16 * 8));
        }
    };
    auto issueV = [&](int kt) {
#pragma unroll
        for (int i = 0; i < 8; i++) {
            int e = t + i * 256;
            int key = e >> 5, c16 = e & 31;
            cp16(swz512(sb + OV, key, c16),
                 (const void*)(g_Vf + qkvoff +
                 ((long)(posbase + (kt * 64 + key) * r)) * DD + c16 * 8));
        }
    };

    // prologue: Q tile + K(0) in ONE commit group
    {
#pragma unroll
        for (int i = 0; i < 8; i++) {
            int e = t + i * 256;
            int row = e >> 5, c16 = e & 31;
            cp16(swz512(sb + OQ, row, c16),
                 (const void*)(g_Qf + qkvoff +
                 ((long)(posbase + (qt * 64 + row) * r)) * DD + c16 * 8));
        }
        issueK(0);
        CP_COMMIT();
    }

    const int g = lane >> 2, cpair = 2 * (lane & 3);
    const int wq = wid & 3, wk = wid >> 2;
    float accd[4][4][4];
#pragma unroll
    for (int mt = 0; mt < 4; mt++)
#pragma unroll
        for (int nt = 0; nt < 4; nt++)
#pragma unroll
            for (int c = 0; c < 4; c++) accd[mt][nt][c] = 0.f;
    float rs0 = 0.f, rs1 = 0.f;

    for (int kt = 0; kt <= qt; kt++) {
        CP_WAIT0();                               // K(kt) (+Q on kt=0) landed (mine)
        __syncthreads();                          // all K landed; prev PV done -> V buf free

        issueV(kt); CP_COMMIT();                  // overlaps S phase

        // ---- S = Q K^T: warp does 16q x 32k, single fp16 term -------------
        float sacc[4][4];
#pragma unroll
        for (int nt = 0; nt < 4; nt++)
#pragma unroll
            for (int c = 0; c < 4; c++) sacc[nt][c] = 0.f;
#pragma unroll 4
        for (int kp = 0; kp < 8; kp++) {
            uint32_t ah0[4], ah1[4];
            ldsm4(ah0, aAddr(sb + OQ, 512, wq * 16, 2 * kp,     lane));
            ldsm4(ah1, aAddr(sb + OQ, 512, wq * 16, 2 * kp + 1, lane));
#pragma unroll
            for (int nt = 0; nt < 4; nt++) {
                uint32_t bh[4];
                ldsm4(bh, b4Addr(sb + OK, 512, wk * 32 + nt * 8, kp, lane));
                mma_fp16(sacc[nt], ah0, bh[0], bh[1]);
                mma_fp16(sacc[nt], ah1, bh[2], bh[3]);
            }
        }

        // ---- softmax: mask, exp, row-sum, pack P (single fp16) -------------
        const int prow0 = wq * 16 + g, prow1 = prow0 + 8;
        const int qrow0 = qt * 64 + prow0, qrow1 = qt * 64 + prow1;
#pragma unroll
        for (int nt = 0; nt < 4; nt++) {
            int kcol = wk * 32 + nt * 8 + cpair;
            int kg = kt * 64 + kcol;
            float p00 = (kg     <= qrow0) ? __expf(sacc[nt][0]) : 0.f;
            float p01 = (kg + 1 <= qrow0) ? __expf(sacc[nt][1]) : 0.f;
            float p10 = (kg     <= qrow1) ? __expf(sacc[nt][2]) : 0.f;
            float p11 = (kg + 1 <= qrow1) ? __expf(sacc[nt][3]) : 0.f;
            rs0 += p00 + p01;
            rs1 += p10 + p11;
            __half2 h0 = __floats2half2_rn(p00, p01);
            __half2 h1 = __floats2half2_rn(p10, p11);
            uint32_t ob0 = prow0 * 128 + ((uint32_t)((kcol >> 3) ^ (prow0 & 7)) << 4)
                         + (kcol & 7) * 2;
            uint32_t ob1 = prow1 * 128 + ((uint32_t)((kcol >> 3) ^ (prow1 & 7)) << 4)
                         + (kcol & 7) * 2;
            *(__half2*)(smem + OP + ob0) = h0;
            *(__half2*)(smem + OP + ob1) = h1;
        }
        __syncthreads();                          // P visible; K buf free

        // ---- prefetch next K (overlaps PV), then wait V --------------------
        if (kt < qt) { issueK(kt + 1); CP_COMMIT(); CP_WAIT1(); }
        else CP_WAIT0();
        __syncthreads();                          // V visible to all

        // ---- D += P V: warp owns 32 d-cols; B-frags from key-major V via
        //      ldmatrix.trans (one ldsm4t = k16 x two n8 tiles) ---------------
        const int n0 = wid * 32;
        const int c16b = n0 >> 3;
#pragma unroll
        for (int kp = 0; kp < 4; kp++) {          // 16 keys per step
            uint32_t bt0[4], bt1[4];
            ldsm4t(bt0, bTAddr(sb + OV, 512, kp * 16, c16b,     lane));
            ldsm4t(bt1, bTAddr(sb + OV, 512, kp * 16, c16b + 2, lane));
#pragma unroll
            for (int mt = 0; mt < 4; mt++) {
                uint32_t ah[4];
                ldsm4(ah, aAddr(sb + OP, 128, mt * 16, kp, lane));
                mma_fp16(accd[mt][0], ah, bt0[0], bt0[1]);
                mma_fp16(accd[mt][1], ah, bt0[2], bt0[3]);
                mma_fp16(accd[mt][2], ah, bt1[0], bt1[1]);
                mma_fp16(accd[mt][3], ah, bt1[2], bt1[3]);
            }
        }
    }

    // ---- epilogue ---------------------------------------------------------
    rs0 += __shfl_xor_sync(0xffffffffu, rs0, 1);
    rs0 += __shfl_xor_sync(0xffffffffu, rs0, 2);
    rs1 += __shfl_xor_sync(0xffffffffu, rs1, 1);
    rs1 += __shfl_xor_sync(0xffffffffu, rs1, 2);
    if ((lane & 3) == 0) {
        lsum2[wk * 64 + wq * 16 + g]     = rs0;
        lsum2[wk * 64 + wq * 16 + g + 8] = rs1;
    }
    __syncthreads();

#pragma unroll
    for (int mt = 0; mt < 4; mt++) {
        int lr0 = mt * 16 + g, lr1 = lr0 + 8;
        float inv0 = 1.0f / (lsum2[lr0] + lsum2[64 + lr0]);
        float inv1 = 1.0f / (lsum2[lr1] + lsum2[64 + lr1]);
        long ro0 = (long)(s * LSEG + qt * 64 + lr0) * DD;
        long ro1 = (long)(s * LSEG + qt * 64 + lr1) * DD;
#pragma unroll
        for (int nt = 0; nt < 4; nt++) {
            int col = wid * 32 + nt * 8 + cpair;
            *(float2*)(g_O + ro0 + col) =
                make_float2(accd[mt][nt][0] * inv0, accd[mt][nt][1] * inv0);
            *(float2*)(g_O + ro1 + col) =
                make_float2(accd[mt][nt][2] * inv1, accd[mt][nt][3] * inv1);
        }
    }
    if (t < 64)
        g_den[s * LSEG + qt * 64 + t] = lsum2[t] + lsum2[64 + t];
}

// ================= Phase 3: combine (gather) ================================
__global__ __launch_bounds__(256) void combine_kernel(float* __restrict__ out)
{
    const int token = blockIdx.x * 4 + (threadIdx.x >> 6);
    const int lane  = threadIdx.x & 63;
    const int b = token >> 13, p = token & 8191;

    const int slot0 = (p >> 11) * 4 + b, j0 = p & 2047;
    float d0 = g_den[slot0 * LSEG + j0];
    float sum = d0;
    int slot1 = -1, j1 = 0, slot2 = -1, j2 = 0;
    float d1 = 0.f, d2 = 0.f;
    if ((p & 1) == 0) {
        slot1 = 16 + (p >> 12) * 4 + b; j1 = (p & 4095) >> 1;
        d1 = g_den[slot1 * LSEG + j1]; sum += d1;
    }
    if ((p & 3) == 0) {
        slot2 = 24 + b; j2 = p >> 2;
        d2 = g_den[slot2 * LSEG + j2]; sum += d2;
    }
    const float inv = 1.0f / sum;
    const int c = lane << 2;

    float4 o0 = *(const float4*)(g_O + ((long)slot0 * LSEG + j0) * DD + c);
    float a0 = d0 * inv;
    float4 res;
    res.x = o0.x * a0; res.y = o0.y * a0; res.z = o0.z * a0; res.w = o0.w * a0;
    if (slot1 >= 0) {
        float4 o1 = *(const float4*)(g_O + ((long)slot1 * LSEG + j1) * DD + c);
        float a1 = d1 * inv;
        res.x = fmaf(o1.x, a1, res.x); res.y = fmaf(o1.y, a1, res.y);
        res.z = fmaf(o1.z, a1, res.z); res.w = fmaf(o1.w, a1, res.w);
    }
    if (slot2 >= 0) {
        float4 o2v = *(const float4*)(g_O + ((long)slot2 * LSEG + j2) * DD + c);
        float a2 = d2 * inv;
        res.x = fmaf(o2v.x, a2, res.x); res.y = fmaf(o2v.y, a2, res.y);
        res.z = fmaf(o2v.z, a2, res.z); res.w = fmaf(o2v.w, a2, res.w);
    }
    *(float4*)(out + ((long)b * NN + p) * DD + c) = res;
}

// ================= launch ====================================================
extern "C" void kernel_launch(void* const* d_in, const int* in_sizes, int n_in,
                              void* d_out, int out_size)
{
    (void)in_sizes; (void)n_in; (void)out_size;
    const float* x  = (const float*)d_in[0];
    const float* Wq = (const float*)d_in[1];
    const float* Wk = (const float*)d_in[2];
    const float* Wv = (const float*)d_in[3];

    cudaFuncSetAttribute(qkv_mma_kernel, cudaFuncAttributeMaxDynamicSharedMemorySize,
                         QKV_SMEM);
    cudaFuncSetAttribute(attn_kernel, cudaFuncAttributeMaxDynamicSharedMemorySize,
                         SM_TOTAL);

    split_x_kernel<<<8192, 256>>>(x);
    split_w_kernel<<<dim3(8, 8, 3), 256>>>(Wq, Wk, Wv);
    qkv_mma_kernel<<<dim3(256, 2, 3), 256, QKV_SMEM>>>();
    attn_kernel<<<32 * NSEG, 256, SM_TOTAL>>>();
    combine_kernel<<<8192, 256>>>((float*)d_out);
}